// round 4
// baseline (speedup 1.0000x reference)
#include <cuda_runtime.h>
#include <math.h>

#define BB 32
#define TT 1024
#define DD 512
#define HH 512

// ---------------- scratch (device globals: allocation-free) ----------------
__device__ float g_pre[TT * BB * HH];     // layer-0 input transform + bias, [t][b][j]
__device__ float g_h0[2][BB][HH];         // layer-0 hidden double buffer
__device__ float g_h1[2][BB][HH];         // layer-1 hidden double buffer
__device__ unsigned g_cntA[4 * 128];      // per-batch-group barrier A (h0) counters
__device__ unsigned g_genA[4 * 128];
__device__ unsigned g_cntB[4 * 128];      // per-batch-group barrier B (h1) counters
__device__ unsigned g_genB[4 * 128];

// ---------------- helpers ----------------------------------------------------
__device__ __forceinline__ unsigned ldacq(const unsigned* p) {
    unsigned v;
    asm volatile("ld.acquire.gpu.u32 %0, [%1];" : "=r"(v) : "l"(p) : "memory");
    return v;
}
__device__ __forceinline__ void strel(unsigned* p, unsigned v) {
    asm volatile("st.release.gpu.u32 [%0], %1;" :: "l"(p), "r"(v) : "memory");
}
__device__ __forceinline__ void fma2(unsigned long long& d,
                                     unsigned long long a, unsigned long long b) {
    asm("fma.rn.f32x2 %0, %1, %2, %0;" : "+l"(d) : "l"(a), "l"(b));
}

// ---------------- init: zero recurrent state + barriers ---------------------
__global__ void init_state() {
    int idx = blockIdx.x * blockDim.x + threadIdx.x;
    if (idx < 2 * BB * HH) {
        ((float*)g_h0)[idx] = 0.f;
        ((float*)g_h1)[idx] = 0.f;
    }
    if (idx < 4) {
        g_cntA[idx * 128] = 0; g_genA[idx * 128] = 0;
        g_cntB[idx * 128] = 0; g_genB[idx * 128] = 0;
    }
}

// ---------------- pre-GEMM (layer 0 only): pre[t*B+b][j] = x_row.W[j]+bias --
__global__ __launch_bounds__(256) void gemm_pre(
    const float* __restrict__ X, const float* __restrict__ W,
    const float* __restrict__ b1, const float* __restrict__ b2)
{
    __shared__ float As[16][68];
    __shared__ float Bs[16][68];

    const int m0 = blockIdx.y * 64;
    const int n0 = blockIdx.x * 64;
    const int tid = threadIdx.x;
    const int r  = tid >> 2;
    const int kq = tid & 3;
    const int tx = tid & 15;
    const int ty = tid >> 4;

    const int m = m0 + r;
    const int t = m >> 5, b = m & 31;
    const float* arow = X + ((size_t)b * TT + t) * DD;
    const float* brow = W + (size_t)(n0 + r) * DD;

    float acc[4][4];
#pragma unroll
    for (int i = 0; i < 4; i++)
#pragma unroll
        for (int j = 0; j < 4; j++) acc[i][j] = 0.f;

    float4 a_next = *(const float4*)(arow + kq * 4);
    float4 b_next = *(const float4*)(brow + kq * 4);

    for (int kt = 0; kt < DD / 16; kt++) {
        float4 a = a_next, bv = b_next;
        As[kq*4+0][r] = a.x;  As[kq*4+1][r] = a.y;
        As[kq*4+2][r] = a.z;  As[kq*4+3][r] = a.w;
        Bs[kq*4+0][r] = bv.x; Bs[kq*4+1][r] = bv.y;
        Bs[kq*4+2][r] = bv.z; Bs[kq*4+3][r] = bv.w;
        __syncthreads();
        if (kt + 1 < DD / 16) {
            a_next = *(const float4*)(arow + (kt + 1) * 16 + kq * 4);
            b_next = *(const float4*)(brow + (kt + 1) * 16 + kq * 4);
        }
#pragma unroll
        for (int k = 0; k < 16; k++) {
            float4 av = *(const float4*)&As[k][ty * 4];
            float4 bw = *(const float4*)&Bs[k][tx * 4];
            float am[4] = {av.x, av.y, av.z, av.w};
            float bn[4] = {bw.x, bw.y, bw.z, bw.w};
#pragma unroll
            for (int i = 0; i < 4; i++)
#pragma unroll
                for (int j = 0; j < 4; j++) acc[i][j] += am[i] * bn[j];
        }
        __syncthreads();
    }

    float bias[4];
#pragma unroll
    for (int j = 0; j < 4; j++) {
        int n = n0 + tx * 4 + j;
        bias[j] = b1[n] + b2[n];
    }
#pragma unroll
    for (int i = 0; i < 4; i++) {
        int mo = m0 + ty * 4 + i;
        float4 v;
        v.x = acc[i][0] + bias[0];
        v.y = acc[i][1] + bias[1];
        v.z = acc[i][2] + bias[2];
        v.w = acc[i][3] + bias[3];
        *(float4*)&g_pre[(size_t)mo * HH + n0 + tx * 4] = v;
    }
}

// ---------------- fused 2-layer persistent recurrence (split-phase) ---------
// 128 CTAs = 32 j-groups (16 rows) x 4 batch-groups (8 batches). 384 threads.
// Round r = 0..TT+1:
//   Phase A (critical, r<TT):  h0[r] = tanh(pre[r] + Whh0 @ h0[r-1]); arrive A
//   Shadow  (r>=2, t1=r-2):    h1[t1] = tanh(b1 + Wih1 @ h0[t1] + Whh1 @ h1[t1-1])
//   Layer 1 lags 2 rounds, so its inputs are >=1 barrier old (slack via B barrier).
#define WP 520
#define HP 516
#define RPA 17
#define RPC 9
#define HT (8 * HP)
#define SMEM_FUSED ((48*WP + 3*HT + 128*RPA + 128*RPA + 128*RPC + 16) * 4)

__global__ __launch_bounds__(384, 1) void rnn_fused(
    const float* __restrict__ Whh0, const float* __restrict__ Wih1,
    const float* __restrict__ Whh1, const float* __restrict__ bih1,
    const float* __restrict__ bhh1, float* __restrict__ out)
{
    extern __shared__ float sm[];
    float* Ws   = sm;                      // 48 x WP (16 Whh0, 16 Wih1, 16 Whh1)
    float* Hs0  = Ws + 48 * WP;            // 2 tiles of 8 x HP (rotating h0)
    float* Hs1  = Hs0 + 2 * HT;            // 8 x HP (h1[r-3])
    float* red0 = Hs1 + HT;                // 128 x RPA
    float* red1 = red0 + 128 * RPA;        // 128 x RPA
    float* red2 = red1 + 128 * RPA;        // 128 x RPC
    float* b1s  = red2 + 128 * RPC;        // 16

    const int tid  = threadIdx.x;
    const int wid  = tid >> 5;
    const int lane = tid & 31;
    const int bg = blockIdx.x >> 5;        // 0..3
    const int jg = blockIdx.x & 31;        // 0..31

    const int jq   = lane & 3;
    const int bq   = (lane >> 2) & 3;
    const int kshi = lane >> 4;            // 0..1
    const int ks16 = wid * 2 + kshi;       // warps 0..7 -> 16 k-slices (mat0/mat1)
    const int ks8  = (wid - 8) * 2 + kshi; // warps 8..11 -> 8 k-slices (mat2)

    // ---- load stacked weight slice into smem (once) ----
    for (int i = tid; i < 48 * 128; i += 384) {
        int row = i >> 7, kq = i & 127;
        const float* src = (row < 16) ? Whh0 + (size_t)(jg * 16 + row) * HH
                         : (row < 32) ? Wih1 + (size_t)(jg * 16 + row - 16) * HH
                                      : Whh1 + (size_t)(jg * 16 + row - 32) * HH;
        *(float4*)&Ws[row * WP + kq * 4] = *(const float4*)(src + kq * 4);
    }
    if (tid < 16) b1s[tid] = bih1[jg * 16 + tid] + bhh1[jg * 16 + tid];
    // zero the 3 h tiles (h "virtual zeros" for early rounds)
    for (int i = tid; i < 3 * 8 * 128; i += 384) {
        int tile = i / 1024, rem = i % 1024, b = rem >> 7, kq = rem & 127;
        float4 z = {0.f, 0.f, 0.f, 0.f};
        *(float4*)&Hs0[tile * HT + b * HP + kq * 4] = z;   // tile 2 == Hs1
    }
    __syncthreads();

    unsigned* cntA = &g_cntA[bg * 128];
    unsigned* genA = &g_genA[bg * 128];
    unsigned* cntB = &g_cntB[bg * 128];
    unsigned* genB = &g_genB[bg * 128];

    const int ej = tid & 15;               // epilogue j (within slice)
    const int eb = (tid >> 4) & 7;         // epilogue b (within group)
    const int gb = bg * 8 + eb;
    const int gj = jg * 16 + ej;

    float pv = (tid < 128) ? g_pre[((size_t)0 * BB + gb) * HH + gj] : 0.f;

    for (int r = 0; r <= TT + 1; r++) {
        float* Hs0c = Hs0 + (r & 1) * HT;         // will hold h0[r-1]
        float* Hs0p = Hs0 + ((r + 1) & 1) * HT;   // holds h0[r-2]

        // ---- A1: wait for h0[r-1] ----
        if (r > 0 && r <= TT) {
            if (tid == 0) { while (ldacq(genA) < (unsigned)r) { } }
            __syncthreads();
        }
        // ---- A2: stage h0[r-1] ----
        if (r >= 1 && r <= TT) {
            for (int i = tid; i < 1024; i += 384) {
                int b = i >> 7, kq = i & 127;
                *(float4*)&Hs0c[b * HP + kq * 4] =
                    *(const float4*)&g_h0[(r - 1) & 1][bg * 8 + b][kq * 4];
            }
        }
        __syncthreads();

        // ---- A4: mat0 = Whh0 @ h0[r-1]  (warps 0..7, 16 k-slices) ----
        if (r < TT && wid < 8) {
            const float* wb = Ws + jq * WP + ks16 * 4;
            const float* hb = Hs0c + (bq * 2) * HP + ks16 * 4;
            unsigned long long acc[4][2];
#pragma unroll
            for (int a = 0; a < 4; a++) { acc[a][0] = 0ull; acc[a][1] = 0ull; }
#pragma unroll
            for (int i = 0; i < 8; i++) {
                const float* wk = wb + i * 64;
                const float* hk = hb + i * 64;
                ulonglong2 hA = *(const ulonglong2*)hk;
                ulonglong2 hB = *(const ulonglong2*)(hk + HP);
#pragma unroll
                for (int jj = 0; jj < 4; jj++) {
                    ulonglong2 w = *(const ulonglong2*)(wk + jj * 4 * WP);
                    fma2(acc[jj][0], w.x, hA.x); fma2(acc[jj][0], w.y, hA.y);
                    fma2(acc[jj][1], w.x, hB.x); fma2(acc[jj][1], w.y, hB.y);
                }
            }
#pragma unroll
            for (int jj = 0; jj < 4; jj++)
#pragma unroll
                for (int bb = 0; bb < 2; bb++) {
                    unsigned long long v = acc[jj][bb];
                    float s = __uint_as_float((unsigned)v)
                            + __uint_as_float((unsigned)(v >> 32));
                    red0[((jj * 4 + jq) * 8 + bq * 2 + bb) * RPA + ks16] = s;
                }
        }
        __syncthreads();

        // ---- A6: epilogue layer 0 ----
        if (r < TT && tid < 128) {
            float s = pv;
            const float* rb = red0 + ((size_t)ej * 8 + eb) * RPA;
#pragma unroll
            for (int p = 0; p < 16; p++) s += rb[p];
            float hn = tanhf(s);
            g_h0[r & 1][gb][gj] = hn;
            if (r == TT - 1)
                out[(size_t)BB * TT * HH + (size_t)gb * HH + gj] = hn;
            __threadfence();
        }
        __syncthreads();
        // ---- A7: arrive A (split-phase) + wait B for shadow staging ----
        if (tid == 0) {
            if (r <= TT) {
                if (atomicAdd(cntA, 1u) == (unsigned)(r * 32 + 31))
                    strel(genA, (unsigned)(r + 1));
            }
            if (r >= 3) { while (ldacq(genB) < (unsigned)r) { } }
        }
        __syncthreads();

        // ---- S3: stage h1[r-3] ----
        if (r >= 3) {
            for (int i = tid; i < 1024; i += 384) {
                int b = i >> 7, kq = i & 127;
                *(float4*)&Hs1[b * HP + kq * 4] =
                    *(const float4*)&g_h1[(r - 3) & 1][bg * 8 + b][kq * 4];
            }
        }
        __syncthreads();

        // ---- S5: mat1 = Wih1 @ h0[r-2] (warps 0..7), mat2 = Whh1 @ h1[r-3] (8..11)
        if (r >= 2) {
            if (wid < 8) {
                const float* wb = Ws + (16 + jq) * WP + ks16 * 4;
                const float* hb = Hs0p + (bq * 2) * HP + ks16 * 4;
                unsigned long long acc[4][2];
#pragma unroll
                for (int a = 0; a < 4; a++) { acc[a][0] = 0ull; acc[a][1] = 0ull; }
#pragma unroll
                for (int i = 0; i < 8; i++) {
                    const float* wk = wb + i * 64;
                    const float* hk = hb + i * 64;
                    ulonglong2 hA = *(const ulonglong2*)hk;
                    ulonglong2 hB = *(const ulonglong2*)(hk + HP);
#pragma unroll
                    for (int jj = 0; jj < 4; jj++) {
                        ulonglong2 w = *(const ulonglong2*)(wk + jj * 4 * WP);
                        fma2(acc[jj][0], w.x, hA.x); fma2(acc[jj][0], w.y, hA.y);
                        fma2(acc[jj][1], w.x, hB.x); fma2(acc[jj][1], w.y, hB.y);
                    }
                }
#pragma unroll
                for (int jj = 0; jj < 4; jj++)
#pragma unroll
                    for (int bb = 0; bb < 2; bb++) {
                        unsigned long long v = acc[jj][bb];
                        float s = __uint_as_float((unsigned)v)
                                + __uint_as_float((unsigned)(v >> 32));
                        red1[((jj * 4 + jq) * 8 + bq * 2 + bb) * RPA + ks16] = s;
                    }
            } else {
                const float* wb = Ws + (32 + jq) * WP + ks8 * 4;
                const float* hb = Hs1 + (bq * 2) * HP + ks8 * 4;
                unsigned long long acc[4][2];
#pragma unroll
                for (int a = 0; a < 4; a++) { acc[a][0] = 0ull; acc[a][1] = 0ull; }
#pragma unroll
                for (int i = 0; i < 16; i++) {
                    const float* wk = wb + i * 32;
                    const float* hk = hb + i * 32;
                    ulonglong2 hA = *(const ulonglong2*)hk;
                    ulonglong2 hB = *(const ulonglong2*)(hk + HP);
#pragma unroll
                    for (int jj = 0; jj < 4; jj++) {
                        ulonglong2 w = *(const ulonglong2*)(wk + jj * 4 * WP);
                        fma2(acc[jj][0], w.x, hA.x); fma2(acc[jj][0], w.y, hA.y);
                        fma2(acc[jj][1], w.x, hB.x); fma2(acc[jj][1], w.y, hB.y);
                    }
                }
#pragma unroll
                for (int jj = 0; jj < 4; jj++)
#pragma unroll
                    for (int bb = 0; bb < 2; bb++) {
                        unsigned long long v = acc[jj][bb];
                        float s = __uint_as_float((unsigned)v)
                                + __uint_as_float((unsigned)(v >> 32));
                        red2[((jj * 4 + jq) * 8 + bq * 2 + bb) * RPC + ks8] = s;
                    }
            }
        }
        __syncthreads();

        // ---- S7: epilogue layer 1 (t1 = r-2) + pv prefetch ----
        if (r >= 2 && tid >= 128 && tid < 256) {
            const int t1 = r - 2;
            float s = b1s[ej];
            const float* rb1 = red1 + ((size_t)ej * 8 + eb) * RPA;
            const float* rb2 = red2 + ((size_t)ej * 8 + eb) * RPC;
#pragma unroll
            for (int p = 0; p < 16; p++) s += rb1[p];
#pragma unroll
            for (int p = 0; p < 8; p++) s += rb2[p];
            float hn = tanhf(s);
            out[((size_t)gb * TT + t1) * HH + gj] = hn;
            g_h1[t1 & 1][gb][gj] = hn;
            if (t1 == TT - 1)
                out[(size_t)BB * TT * HH + (size_t)BB * HH + (size_t)gb * HH + gj] = hn;
            __threadfence();
        }
        if (tid < 128 && r + 1 < TT)
            pv = g_pre[((size_t)(r + 1) * BB + gb) * HH + gj];
        __syncthreads();
        if (tid == 0) {
            if (atomicAdd(cntB, 1u) == (unsigned)(r * 32 + 31))
                strel(genB, (unsigned)(r + 1));
        }
    }
}

// ---------------- launch ----------------------------------------------------
extern "C" void kernel_launch(void* const* d_in, const int* in_sizes, int n_in,
                              void* d_out, int out_size)
{
    (void)in_sizes; (void)n_in; (void)out_size;
    const float* x    = (const float*)d_in[0];
    const float* wih0 = (const float*)d_in[1];
    const float* whh0 = (const float*)d_in[2];
    const float* bih0 = (const float*)d_in[3];
    const float* bhh0 = (const float*)d_in[4];
    const float* wih1 = (const float*)d_in[5];
    const float* whh1 = (const float*)d_in[6];
    const float* bih1 = (const float*)d_in[7];
    const float* bhh1 = (const float*)d_in[8];
    float* out = (float*)d_out;

    cudaFuncSetAttribute(rnn_fused,
                         cudaFuncAttributeMaxDynamicSharedMemorySize, SMEM_FUSED);

    init_state<<<128, 256>>>();

    dim3 gemmGrid(HH / 64, (TT * BB) / 64);   // (8, 512)
    gemm_pre<<<gemmGrid, 256>>>(x, wih0, bih0, bhh0);

    rnn_fused<<<128, 384, SMEM_FUSED>>>(whh0, wih1, whh1, bih1, bhh1, out);
}

// round 5
// speedup vs baseline: 1.0241x; 1.0241x over previous
#include <cuda_runtime.h>
#include <math.h>

#define BB 32
#define TT 1024
#define DD 512
#define HH 512

// ---------------- scratch (device globals: allocation-free) ----------------
__device__ float g_pre[TT * BB * HH];      // 64MB: layer-0 input transform + bias
__device__ float g_h0hist[TT * BB * HH];   // 64MB: full h0 history (= y0)
__device__ float g_h1[2][BB][HH];          // layer-1 hidden double buffer
__device__ unsigned g_sub [2 * 4 * 4 * 32];  // [chain][bg][sub] stride 32
__device__ unsigned g_mainc[2 * 4 * 32];     // [chain][bg]
__device__ unsigned g_genc [2 * 4 * 32];     // [chain][bg]

// ---------------- helpers ----------------------------------------------------
__device__ __forceinline__ unsigned ldacq(const unsigned* p) {
    unsigned v;
    asm volatile("ld.acquire.gpu.u32 %0, [%1];" : "=r"(v) : "l"(p) : "memory");
    return v;
}
__device__ __forceinline__ void strel(unsigned* p, unsigned v) {
    asm volatile("st.release.gpu.u32 [%0], %1;" :: "l"(p), "r"(v) : "memory");
}
__device__ __forceinline__ unsigned atom_acqrel(unsigned* p) {
    unsigned v;
    asm volatile("atom.add.acq_rel.gpu.u32 %0, [%1], 1;" : "=r"(v) : "l"(p) : "memory");
    return v;
}
__device__ __forceinline__ void fma2(unsigned long long& d,
                                     unsigned long long a, unsigned long long b) {
    asm("fma.rn.f32x2 %0, %1, %2, %0;" : "+l"(d) : "l"(a), "l"(b));
}
// two-level arrival: 4 subs x 8 CTAs, then main x 4; last releases gen = t+1
__device__ __forceinline__ void arrive(unsigned* subc, unsigned* mainc,
                                       unsigned* gen, int t) {
    unsigned a = atom_acqrel(subc);
    if ((a & 7u) == 7u) {
        unsigned m = atom_acqrel(mainc);
        if ((m & 3u) == 3u) strel(gen, (unsigned)(t + 1));
    }
}

// ---------------- init: zero barrier state -----------------------------------
__global__ void init_state() {
    int idx = blockIdx.x * blockDim.x + threadIdx.x;
    if (idx < 2 * 4 * 4 * 32) g_sub[idx] = 0;
    if (idx < 2 * 4 * 32) { g_mainc[idx] = 0; g_genc[idx] = 0; }
}

// ---------------- pre-GEMM (layer 0): pre[t*B+b][j] = x_row.W[j]+bias --------
__global__ __launch_bounds__(256) void gemm_pre(
    const float* __restrict__ X, const float* __restrict__ W,
    const float* __restrict__ b1, const float* __restrict__ b2)
{
    __shared__ float As[16][68];
    __shared__ float Bs[16][68];

    const int m0 = blockIdx.y * 64;
    const int n0 = blockIdx.x * 64;
    const int tid = threadIdx.x;
    const int r  = tid >> 2;
    const int kq = tid & 3;
    const int tx = tid & 15;
    const int ty = tid >> 4;

    const int m = m0 + r;
    const int t = m >> 5, b = m & 31;
    const float* arow = X + ((size_t)b * TT + t) * DD;
    const float* brow = W + (size_t)(n0 + r) * DD;

    float acc[4][4];
#pragma unroll
    for (int i = 0; i < 4; i++)
#pragma unroll
        for (int j = 0; j < 4; j++) acc[i][j] = 0.f;

    float4 a_next = *(const float4*)(arow + kq * 4);
    float4 b_next = *(const float4*)(brow + kq * 4);

    for (int kt = 0; kt < DD / 16; kt++) {
        float4 a = a_next, bv = b_next;
        As[kq*4+0][r] = a.x;  As[kq*4+1][r] = a.y;
        As[kq*4+2][r] = a.z;  As[kq*4+3][r] = a.w;
        Bs[kq*4+0][r] = bv.x; Bs[kq*4+1][r] = bv.y;
        Bs[kq*4+2][r] = bv.z; Bs[kq*4+3][r] = bv.w;
        __syncthreads();
        if (kt + 1 < DD / 16) {
            a_next = *(const float4*)(arow + (kt + 1) * 16 + kq * 4);
            b_next = *(const float4*)(brow + (kt + 1) * 16 + kq * 4);
        }
#pragma unroll
        for (int k = 0; k < 16; k++) {
            float4 av = *(const float4*)&As[k][ty * 4];
            float4 bw = *(const float4*)&Bs[k][tx * 4];
            float am[4] = {av.x, av.y, av.z, av.w};
            float bn[4] = {bw.x, bw.y, bw.z, bw.w};
#pragma unroll
            for (int i = 0; i < 4; i++)
#pragma unroll
                for (int j = 0; j < 4; j++) acc[i][j] += am[i] * bn[j];
        }
        __syncthreads();
    }

    float bias[4];
#pragma unroll
    for (int j = 0; j < 4; j++) {
        int n = n0 + tx * 4 + j;
        bias[j] = b1[n] + b2[n];
    }
#pragma unroll
    for (int i = 0; i < 4; i++) {
        int mo = m0 + ty * 4 + i;
        float4 v;
        v.x = acc[i][0] + bias[0];
        v.y = acc[i][1] + bias[1];
        v.z = acc[i][2] + bias[2];
        v.w = acc[i][3] + bias[3];
        *(float4*)&g_pre[(size_t)mo * HH + n0 + tx * 4] = v;
    }
}

// ---------------- two parallel persistent chains -----------------------------
// 256 CTAs: bid<128 -> layer-0 chain; bid>=128 -> layer-1 chain.
// Each chain: 32 j-groups (16 rows) x 4 batch-groups (8 batches), 256 thr.
// L0 round t: wait gen0>=t; h0[t] = tanh(pre[t] + Whh0 @ h0[t-1]); arrive.
// L1 round t: wait gen0>=t+1 (h0[t] ready) & gen1>=t;
//             h1[t] = tanh(b1 + Wih1 @ h0[t] + Whh1 @ h1[t-1]); arrive.
#define WP 520
#define HP 516
#define RPA 17
#define RPB 9
#define SMEM_CHAIN ((32*WP + 2*8*HP + 2*128*RPB + 32) * 4)

__global__ __launch_bounds__(256, 2) void rnn_chains(
    const float* __restrict__ Whh0, const float* __restrict__ Wih1,
    const float* __restrict__ Whh1, const float* __restrict__ bih1,
    const float* __restrict__ bhh1, float* __restrict__ out)
{
    extern __shared__ float sm[];
    const int bid = blockIdx.x;
    const int chain = bid >> 7;
    const int idx = bid & 127;
    const int jg = idx & 31, bg = idx >> 5;
    const int tid = threadIdx.x;
    const int wid = tid >> 5, lane = tid & 31;
    const int jq = lane & 3, bq = (lane >> 2) & 3, kshi = lane >> 4;

    unsigned* subc  = &g_sub  [((chain * 4 + bg) * 4 + (jg >> 3)) * 32];
    unsigned* mainc = &g_mainc[(chain * 4 + bg) * 32];
    unsigned* genS  = &g_genc [(chain * 4 + bg) * 32];
    unsigned* gen0  = &g_genc [(0 * 4 + bg) * 32];

    const int ej = tid & 15, eb = (tid >> 4) & 7;
    const int gb = bg * 8 + eb, gj = jg * 16 + ej;
    const size_t HIDOFF = (size_t)BB * TT * HH;

    if (chain == 0) {
        // ----------------- layer-0 chain -----------------
        float* Ws  = sm;
        float* Hs  = sm + 16 * WP;
        float* red = Hs + 8 * HP;

        for (int i = tid; i < 16 * 128; i += 256) {
            int row = i >> 7, kq = i & 127;
            *(float4*)&Ws[row * WP + kq * 4] =
                *(const float4*)(Whh0 + (size_t)(jg * 16 + row) * HH + kq * 4);
        }
        for (int i = tid; i < 8 * 128; i += 256) {
            int b = i >> 7, kq = i & 127;
            float4 z = {0.f, 0.f, 0.f, 0.f};
            *(float4*)&Hs[b * HP + kq * 4] = z;
        }
        __syncthreads();

        const int ks = wid * 2 + kshi;               // 0..15
        const float* wb = Ws + jq * WP + ks * 4;
        const float* hb = Hs + (bq * 2) * HP + ks * 4;

        for (int t = 0; t < TT; t++) {
            if (t > 0) {
                if (tid == 0) { while (ldacq(genS) < (unsigned)t) { } }
                __syncthreads();
                for (int i = tid; i < 1024; i += 256) {
                    int b = i >> 7, kq = i & 127;
                    *(float4*)&Hs[b * HP + kq * 4] =
                        *(const float4*)&g_h0hist[((size_t)(t-1) * BB + bg * 8 + b) * HH + kq * 4];
                }
            }
            float pv = (tid < 128) ? g_pre[((size_t)t * BB + gb) * HH + gj] : 0.f;
            __syncthreads();

            unsigned long long acc[4][2];
#pragma unroll
            for (int a = 0; a < 4; a++) { acc[a][0] = 0ull; acc[a][1] = 0ull; }
#pragma unroll
            for (int i = 0; i < 8; i++) {
                const float* wk = wb + i * 64;
                const float* hk = hb + i * 64;
                ulonglong2 hA = *(const ulonglong2*)hk;
                ulonglong2 hB = *(const ulonglong2*)(hk + HP);
#pragma unroll
                for (int jj = 0; jj < 4; jj++) {
                    ulonglong2 w = *(const ulonglong2*)(wk + jj * 4 * WP);
                    fma2(acc[jj][0], w.x, hA.x); fma2(acc[jj][0], w.y, hA.y);
                    fma2(acc[jj][1], w.x, hB.x); fma2(acc[jj][1], w.y, hB.y);
                }
            }
#pragma unroll
            for (int jj = 0; jj < 4; jj++)
#pragma unroll
                for (int bb = 0; bb < 2; bb++) {
                    unsigned long long v = acc[jj][bb];
                    float s = __uint_as_float((unsigned)v)
                            + __uint_as_float((unsigned)(v >> 32));
                    red[((jj * 4 + jq) * 8 + bq * 2 + bb) * RPA + ks] = s;
                }
            __syncthreads();

            if (tid < 128) {
                float s = pv;
                const float* rb = red + (ej * 8 + eb) * RPA;
#pragma unroll
                for (int p = 0; p < 16; p++) s += rb[p];
                float hn = tanhf(s);
                g_h0hist[((size_t)t * BB + gb) * HH + gj] = hn;
                if (t == TT - 1) out[HIDOFF + (size_t)gb * HH + gj] = hn;
            }
            __syncthreads();
            if (tid == 0) arrive(subc, mainc, genS, t);
        }
    } else {
        // ----------------- layer-1 chain -----------------
        float* Ws   = sm;                    // 32 rows: 16 Wih1 then 16 Whh1
        float* HsA  = sm + 32 * WP;          // h0[t]
        float* HsB  = HsA + 8 * HP;          // h1[t-1]
        float* red1 = HsB + 8 * HP;
        float* red2 = red1 + 128 * RPB;
        float* b1s  = red2 + 128 * RPB;

        for (int i = tid; i < 32 * 128; i += 256) {
            int row = i >> 7, kq = i & 127;
            const float* src = (row < 16)
                ? Wih1 + (size_t)(jg * 16 + row) * HH
                : Whh1 + (size_t)(jg * 16 + row - 16) * HH;
            *(float4*)&Ws[row * WP + kq * 4] = *(const float4*)(src + kq * 4);
        }
        for (int i = tid; i < 8 * 128; i += 256) {
            int b = i >> 7, kq = i & 127;
            float4 z = {0.f, 0.f, 0.f, 0.f};
            *(float4*)&HsB[b * HP + kq * 4] = z;
        }
        if (tid < 16) b1s[tid] = bih1[jg * 16 + tid] + bhh1[jg * 16 + tid];
        __syncthreads();

        const int ks = (wid & 3) * 2 + kshi;          // 0..7
        const int m2 = (wid >> 2);                    // 0: mat1, 1: mat2
        const float* wb = Ws + (m2 * 16 + jq) * WP + ks * 4;
        const float* hb = (m2 ? HsB : HsA) + (bq * 2) * HP + ks * 4;
        float* redw = m2 ? red2 : red1;

        for (int t = 0; t < TT; t++) {
            if (tid == 0) {
                while (ldacq(gen0) < (unsigned)(t + 1)) { }     // h0[t] ready
                if (t > 0) { while (ldacq(genS) < (unsigned)t) { } }
            }
            __syncthreads();
            for (int i = tid; i < 1024; i += 256) {
                int b = i >> 7, kq = i & 127;
                *(float4*)&HsA[b * HP + kq * 4] =
                    *(const float4*)&g_h0hist[((size_t)t * BB + bg * 8 + b) * HH + kq * 4];
            }
            if (t > 0) {
                for (int i = tid; i < 1024; i += 256) {
                    int b = i >> 7, kq = i & 127;
                    *(float4*)&HsB[b * HP + kq * 4] =
                        *(const float4*)&g_h1[(t - 1) & 1][bg * 8 + b][kq * 4];
                }
            }
            __syncthreads();

            unsigned long long acc[4][2];
#pragma unroll
            for (int a = 0; a < 4; a++) { acc[a][0] = 0ull; acc[a][1] = 0ull; }
#pragma unroll
            for (int i = 0; i < 16; i++) {
                const float* wk = wb + i * 32;
                const float* hk = hb + i * 32;
                ulonglong2 hA = *(const ulonglong2*)hk;
                ulonglong2 hB = *(const ulonglong2*)(hk + HP);
#pragma unroll
                for (int jj = 0; jj < 4; jj++) {
                    ulonglong2 w = *(const ulonglong2*)(wk + jj * 4 * WP);
                    fma2(acc[jj][0], w.x, hA.x); fma2(acc[jj][0], w.y, hA.y);
                    fma2(acc[jj][1], w.x, hB.x); fma2(acc[jj][1], w.y, hB.y);
                }
            }
#pragma unroll
            for (int jj = 0; jj < 4; jj++)
#pragma unroll
                for (int bb = 0; bb < 2; bb++) {
                    unsigned long long v = acc[jj][bb];
                    float s = __uint_as_float((unsigned)v)
                            + __uint_as_float((unsigned)(v >> 32));
                    redw[((jj * 4 + jq) * 8 + bq * 2 + bb) * RPB + ks] = s;
                }
            __syncthreads();

            if (tid < 128) {
                float s = b1s[ej];
                const float* rb1 = red1 + (ej * 8 + eb) * RPB;
                const float* rb2 = red2 + (ej * 8 + eb) * RPB;
#pragma unroll
                for (int p = 0; p < 8; p++) s += rb1[p] + rb2[p];
                float hn = tanhf(s);
                g_h1[t & 1][gb][gj] = hn;
                out[((size_t)gb * TT + t) * HH + gj] = hn;
                if (t == TT - 1)
                    out[HIDOFF + (size_t)BB * HH + (size_t)gb * HH + gj] = hn;
            }
            __syncthreads();
            if (tid == 0) arrive(subc, mainc, genS, t);
        }
    }
}

// ---------------- launch ----------------------------------------------------
extern "C" void kernel_launch(void* const* d_in, const int* in_sizes, int n_in,
                              void* d_out, int out_size)
{
    (void)in_sizes; (void)n_in; (void)out_size;
    const float* x    = (const float*)d_in[0];
    const float* wih0 = (const float*)d_in[1];
    const float* whh0 = (const float*)d_in[2];
    const float* bih0 = (const float*)d_in[3];
    const float* bhh0 = (const float*)d_in[4];
    const float* wih1 = (const float*)d_in[5];
    const float* whh1 = (const float*)d_in[6];
    const float* bih1 = (const float*)d_in[7];
    const float* bhh1 = (const float*)d_in[8];
    float* out = (float*)d_out;

    cudaFuncSetAttribute(rnn_chains,
                         cudaFuncAttributeMaxDynamicSharedMemorySize, SMEM_CHAIN);

    init_state<<<2, 256>>>();

    dim3 gemmGrid(HH / 64, (TT * BB) / 64);   // (8, 512)
    gemm_pre<<<gemmGrid, 256>>>(x, wih0, bih0, bhh0);

    rnn_chains<<<256, 256, SMEM_CHAIN>>>(whh0, wih1, whh1, bih1, bhh1, out);
}

// round 6
// speedup vs baseline: 1.1250x; 1.0985x over previous
#include <cuda_runtime.h>
#include <math.h>

#define BB 32
#define TT 1024
#define DD 512
#define HH 512

// ---------------- scratch (device globals: allocation-free) ----------------
__device__ float g_pre[TT * BB * HH];     // layer-0 input transform + bias, [t][b][j]
__device__ float g_h0[2][BB][HH];         // layer-0 hidden double buffer
__device__ float g_h1[2][BB][HH];         // layer-1 hidden double buffer
__device__ unsigned g_sub [4 * 4 * 32];   // [bg][sub] stride 32 (4 subs x 8 CTAs)
__device__ unsigned g_main[4 * 32];       // [bg]
__device__ unsigned g_gen [4 * 32];       // [bg]

// ---------------- sync helpers ----------------------------------------------
__device__ __forceinline__ unsigned ldacq(const unsigned* p) {
    unsigned v;
    asm volatile("ld.acquire.gpu.u32 %0, [%1];" : "=r"(v) : "l"(p) : "memory");
    return v;
}
__device__ __forceinline__ void strel(unsigned* p, unsigned v) {
    asm volatile("st.release.gpu.u32 [%0], %1;" :: "l"(p), "r"(v) : "memory");
}
__device__ __forceinline__ unsigned atom_acqrel(unsigned* p) {
    unsigned v;
    asm volatile("atom.add.acq_rel.gpu.u32 %0, [%1], 1;" : "=r"(v) : "l"(p) : "memory");
    return v;
}
__device__ __forceinline__ void fma2(unsigned long long& d,
                                     unsigned long long a, unsigned long long b) {
    asm("fma.rn.f32x2 %0, %1, %2, %0;" : "+l"(d) : "l"(a), "l"(b));
}

// ---------------- init: zero recurrent state + barriers ---------------------
__global__ void init_state() {
    int idx = blockIdx.x * blockDim.x + threadIdx.x;
    if (idx < 2 * BB * HH) {
        ((float*)g_h0)[idx] = 0.f;
        ((float*)g_h1)[idx] = 0.f;
    }
    if (idx < 4 * 4 * 32) g_sub[idx] = 0;
    if (idx < 4 * 32) { g_main[idx] = 0; g_gen[idx] = 0; }
}

// ---------------- pre-GEMM (layer 0 only): pre[t*B+b][j] = x_row.W[j]+bias --
__global__ __launch_bounds__(256) void gemm_pre(
    const float* __restrict__ X, const float* __restrict__ W,
    const float* __restrict__ b1, const float* __restrict__ b2)
{
    __shared__ float As[16][68];
    __shared__ float Bs[16][68];

    const int m0 = blockIdx.y * 64;
    const int n0 = blockIdx.x * 64;
    const int tid = threadIdx.x;
    const int r  = tid >> 2;
    const int kq = tid & 3;
    const int tx = tid & 15;
    const int ty = tid >> 4;

    const int m = m0 + r;
    const int t = m >> 5, b = m & 31;
    const float* arow = X + ((size_t)b * TT + t) * DD;
    const float* brow = W + (size_t)(n0 + r) * DD;

    float acc[4][4];
#pragma unroll
    for (int i = 0; i < 4; i++)
#pragma unroll
        for (int j = 0; j < 4; j++) acc[i][j] = 0.f;

    float4 a_next = *(const float4*)(arow + kq * 4);
    float4 b_next = *(const float4*)(brow + kq * 4);

    for (int kt = 0; kt < DD / 16; kt++) {
        float4 a = a_next, bv = b_next;
        As[kq*4+0][r] = a.x;  As[kq*4+1][r] = a.y;
        As[kq*4+2][r] = a.z;  As[kq*4+3][r] = a.w;
        Bs[kq*4+0][r] = bv.x; Bs[kq*4+1][r] = bv.y;
        Bs[kq*4+2][r] = bv.z; Bs[kq*4+3][r] = bv.w;
        __syncthreads();
        if (kt + 1 < DD / 16) {
            a_next = *(const float4*)(arow + (kt + 1) * 16 + kq * 4);
            b_next = *(const float4*)(brow + (kt + 1) * 16 + kq * 4);
        }
#pragma unroll
        for (int k = 0; k < 16; k++) {
            float4 av = *(const float4*)&As[k][ty * 4];
            float4 bw = *(const float4*)&Bs[k][tx * 4];
            float am[4] = {av.x, av.y, av.z, av.w};
            float bn[4] = {bw.x, bw.y, bw.z, bw.w};
#pragma unroll
            for (int i = 0; i < 4; i++)
#pragma unroll
                for (int j = 0; j < 4; j++) acc[i][j] += am[i] * bn[j];
        }
        __syncthreads();
    }

    float bias[4];
#pragma unroll
    for (int j = 0; j < 4; j++) {
        int n = n0 + tx * 4 + j;
        bias[j] = b1[n] + b2[n];
    }
#pragma unroll
    for (int i = 0; i < 4; i++) {
        int mo = m0 + ty * 4 + i;
        float4 v;
        v.x = acc[i][0] + bias[0];
        v.y = acc[i][1] + bias[1];
        v.z = acc[i][2] + bias[2];
        v.w = acc[i][3] + bias[3];
        *(float4*)&g_pre[(size_t)mo * HH + n0 + tx * 4] = v;
    }
}

// ---------------- fused 2-layer persistent recurrence -----------------------
// 128 CTAs = 32 j-groups (16 rows) x 4 batch-groups (8 batches). 384 threads.
// Round r (r=0..TT):
//   if r <  TT: h0[r]   = tanh(pre[r]       + Whh0 @ h0[r-1])          (mat 0)
//   if r >= 1 : h1[r-1] = tanh(b1 + Wih1 @ h0[r-1] + Whh1 @ h1[r-2])   (mats 1,2)
// Per-batch-group two-level barrier (4 subs x 8, then main x 4) between rounds.
#define WP 520
#define HP 516
#define RP 9
#define SMEM_FUSED ((48*WP + 2*8*HP + 48*8*RP + 16) * 4)

__global__ __launch_bounds__(384, 1) void rnn_fused(
    const float* __restrict__ Whh0, const float* __restrict__ Wih1,
    const float* __restrict__ Whh1, const float* __restrict__ bih1,
    const float* __restrict__ bhh1, float* __restrict__ out)
{
    extern __shared__ float sm[];
    float* Ws  = sm;                     // 48 x WP  (rows: 16 Whh0, 16 Wih1, 16 Whh1)
    float* Hs0 = Ws  + 48 * WP;          // 8 x HP
    float* Hs1 = Hs0 + 8 * HP;           // 8 x HP
    float* red = Hs1 + 8 * HP;           // 48*8*RP partials
    float* b1s = red + 48 * 8 * RP;      // 16 biases

    const int tid  = threadIdx.x;
    const int wid  = tid >> 5;
    const int lane = tid & 31;
    const int bg = blockIdx.x >> 5;      // 0..3
    const int jg = blockIdx.x & 31;      // 0..31

    const int mat = wid % 3;             // SMSP = wid%4 -> each SMSP gets mats {0,1,2}
    const int wom = wid / 3;             // 0..3
    const int jq   = lane & 3;
    const int bq   = (lane >> 2) & 3;
    const int kshi = lane >> 4;
    const int ks   = wom * 2 + kshi;     // 0..7 (k-slice)

    // ---- load stacked weight slice into smem (once) ----
    for (int i = tid; i < 48 * 128; i += 384) {
        int row = i >> 7, kq = i & 127;
        const float* src = (row < 16) ? Whh0 + (size_t)(jg * 16 + row) * HH
                         : (row < 32) ? Wih1 + (size_t)(jg * 16 + row - 16) * HH
                                      : Whh1 + (size_t)(jg * 16 + row - 32) * HH;
        *(float4*)&Ws[row * WP + kq * 4] = *(const float4*)(src + kq * 4);
    }
    if (tid < 16) b1s[tid] = bih1[jg * 16 + tid] + bhh1[jg * 16 + tid];

    unsigned* subc  = &g_sub [(bg * 4 + (jg >> 3)) * 32];
    unsigned* mainc = &g_main[bg * 32];
    unsigned* gen   = &g_gen [bg * 32];

    const int ej = tid & 15;             // epilogue j (within slice)
    const int eb = (tid >> 4) & 7;       // epilogue b (within group)
    const int gb = bg * 8 + eb;          // global batch
    const int gj = jg * 16 + ej;         // global j

    float pv = 0.f;
    if (tid < 128) pv = g_pre[((size_t)0 * BB + gb) * HH + gj];

    const float* wbase = Ws + (mat * 16 + jq) * WP + ks * 4;

    for (int r = 0; r <= TT; r++) {
        const int cur = r & 1, nxt = cur ^ 1;

        // ---- per-warp wait for generation r (h0[r-1], h1[r-2] published) ----
        if (r > 0) {
            if (lane == 0) { while (ldacq(gen) < (unsigned)r) { } }
            __syncwarp();
        }

        // ---- stage h0[r-1], h1[r-2] tiles for this batch group ----
        for (int i = tid; i < 8 * 128; i += 384) {
            int b = i >> 7, kq = i & 127;
            *(float4*)&Hs0[b * HP + kq * 4] = *(const float4*)&g_h0[cur][bg * 8 + b][kq * 4];
            *(float4*)&Hs1[b * HP + kq * 4] = *(const float4*)&g_h1[cur][bg * 8 + b][kq * 4];
        }
        __syncthreads();

        // ---- compute: lane = 4j x 2b micro-tile over its k-slice -----------
        // k coverage: ks*4 + i*32 + {0..3}  (i = 0..15) -> full 512 across ks=0..7
        const float* hbase = ((mat == 2) ? Hs1 : Hs0) + (bq * 2) * HP + ks * 4;
        unsigned long long acc[4][2];
#pragma unroll
        for (int a = 0; a < 4; a++) { acc[a][0] = 0ull; acc[a][1] = 0ull; }

#pragma unroll
        for (int i = 0; i < 16; i++) {
            const float* wk = wbase + i * 32;
            const float* hk = hbase + i * 32;
            ulonglong2 hA = *(const ulonglong2*)hk;
            ulonglong2 hB = *(const ulonglong2*)(hk + HP);
#pragma unroll
            for (int jj = 0; jj < 4; jj++) {
                ulonglong2 w = *(const ulonglong2*)(wk + jj * 4 * WP);
                fma2(acc[jj][0], w.x, hA.x); fma2(acc[jj][0], w.y, hA.y);
                fma2(acc[jj][1], w.x, hB.x); fma2(acc[jj][1], w.y, hB.y);
            }
        }

        // ---- write partial sums ----
#pragma unroll
        for (int jj = 0; jj < 4; jj++)
#pragma unroll
            for (int bb = 0; bb < 2; bb++) {
                unsigned long long v = acc[jj][bb];
                float s = __uint_as_float((unsigned)v)
                        + __uint_as_float((unsigned)(v >> 32));
                red[((mat * 16 + jj * 4 + jq) * 8 + bq * 2 + bb) * RP + ks] = s;
            }
        __syncthreads();

        // ---- epilogue ----
        if (tid < 128) {
            if (r < TT) {
                float s = pv;
                const float* rb = red + ((size_t)ej * 8 + eb) * RP;
#pragma unroll
                for (int p = 0; p < 8; p++) s += rb[p];
                float hn = tanhf(s);
                g_h0[nxt][gb][gj] = hn;
                if (r == TT - 1)
                    out[(size_t)BB * TT * HH + (size_t)gb * HH + gj] = hn;
            }
        } else if (tid < 256) {
            if (r >= 1) {
                float s = b1s[ej];
                const float* rb1 = red + ((size_t)(16 + ej) * 8 + eb) * RP;
                const float* rb2 = red + ((size_t)(32 + ej) * 8 + eb) * RP;
#pragma unroll
                for (int p = 0; p < 8; p++) s += rb1[p] + rb2[p];
                float hn = tanhf(s);
                g_h1[nxt][gb][gj] = hn;
                const int t1 = r - 1;
                out[((size_t)gb * TT + t1) * HH + gj] = hn;
                if (t1 == TT - 1)
                    out[(size_t)BB * TT * HH + (size_t)BB * HH + (size_t)gb * HH + gj] = hn;
            }
        }

        // prefetch next round's pre value (independent of the barrier)
        if (tid < 128 && r + 1 < TT)
            pv = g_pre[((size_t)(r + 1) * BB + gb) * HH + gj];

        // ---- two-level arrival (skip after final round) ----
        if (r < TT) {
            __syncthreads();
            if (tid == 0) {
                unsigned a = atom_acqrel(subc);
                if ((a & 7u) == 7u) {
                    unsigned m = atom_acqrel(mainc);
                    if ((m & 3u) == 3u) strel(gen, (unsigned)(r + 1));
                }
            }
        }
    }
}

// ---------------- launch ----------------------------------------------------
extern "C" void kernel_launch(void* const* d_in, const int* in_sizes, int n_in,
                              void* d_out, int out_size)
{
    (void)in_sizes; (void)n_in; (void)out_size;
    const float* x    = (const float*)d_in[0];
    const float* wih0 = (const float*)d_in[1];
    const float* whh0 = (const float*)d_in[2];
    const float* bih0 = (const float*)d_in[3];
    const float* bhh0 = (const float*)d_in[4];
    const float* wih1 = (const float*)d_in[5];
    const float* whh1 = (const float*)d_in[6];
    const float* bih1 = (const float*)d_in[7];
    const float* bhh1 = (const float*)d_in[8];
    float* out = (float*)d_out;

    cudaFuncSetAttribute(rnn_fused,
                         cudaFuncAttributeMaxDynamicSharedMemorySize, SMEM_FUSED);

    init_state<<<128, 256>>>();

    dim3 gemmGrid(HH / 64, (TT * BB) / 64);   // (8, 512)
    gemm_pre<<<gemmGrid, 256>>>(x, wih0, bih0, bhh0);

    rnn_fused<<<128, 384, SMEM_FUSED>>>(whh0, wih1, whh1, bih1, bhh1, out);
}